// round 16
// baseline (speedup 1.0000x reference)
#include <cuda_runtime.h>
#include <cuda_fp16.h>
#include <math.h>
#include <stdint.h>

// ---------------------------------------------------------------------------
// MoE: T=8192 tokens, D=1024, MLP=4096, E=8, top-2.
// fp16 HMMA path. R16: GEMM2 K-split x4 (atomic epilogue makes it free) to
// kill its 3.5-wave quantization tail. Otherwise identical to R15 (927.8us).
// ---------------------------------------------------------------------------

#define T_TOKENS 8192
#define DIM      1024
#define MLP      4096
#define NEXP     8
#define TK_TOT   (T_TOKENS * 2)

// ---- scratch (device globals; no cudaMalloc allowed) ----
__device__ int   g_count[NEXP];
__device__ int   g_offset[NEXP + 1];
__device__ int   g_fill[NEXP];
__device__ int   g_topki[TK_TOT];
__device__ float g_topkg[TK_TOT];
__device__ int   g_tok[TK_TOT];
__device__ float g_gate[TK_TOT];
__device__ __align__(16) __half g_xh [(size_t)T_TOKENS * DIM];
__device__ __align__(16) __half g_w1t[(size_t)NEXP * MLP * DIM];  // [e][n][k]
__device__ __align__(16) __half g_w2t[(size_t)NEXP * DIM * MLP];  // [e][n][k]
__device__ __align__(16) __half g_Hh [(size_t)TK_TOT * MLP];

// ---------------------------------------------------------------------------
// PTX helpers (sm_80-era instructions only; legal on plain sm_103 target)
// ---------------------------------------------------------------------------
__device__ __forceinline__ uint32_t smem_u32(const void* p) {
    uint32_t a;
    asm("{ .reg .u64 t; cvta.to.shared.u64 t, %1; cvt.u32.u64 %0, t; }" : "=r"(a) : "l"(p));
    return a;
}
__device__ __forceinline__ void cp16(uint32_t dst, const void* src) {
    asm volatile("cp.async.cg.shared.global [%0], [%1], 16;" :: "r"(dst), "l"(src) : "memory");
}
__device__ __forceinline__ void cp_commit() { asm volatile("cp.async.commit_group;" ::: "memory"); }

__device__ __forceinline__ void ldsm_x4(uint32_t* r, uint32_t addr) {
    asm volatile("ldmatrix.sync.aligned.m8n8.x4.shared.b16 {%0,%1,%2,%3}, [%4];"
                 : "=r"(r[0]), "=r"(r[1]), "=r"(r[2]), "=r"(r[3]) : "r"(addr));
}
__device__ __forceinline__ void mma16816(float* c, const uint32_t* a, const uint32_t* b) {
    asm volatile("mma.sync.aligned.m16n8k16.row.col.f32.f16.f16.f32 "
                 "{%0,%1,%2,%3}, {%4,%5,%6,%7}, {%8,%9}, {%0,%1,%2,%3};"
                 : "+f"(c[0]), "+f"(c[1]), "+f"(c[2]), "+f"(c[3])
                 : "r"(a[0]), "r"(a[1]), "r"(a[2]), "r"(a[3]), "r"(b[0]), "r"(b[1]));
}

__device__ __forceinline__ float gelu_exact(float v) {
    return 0.5f * v * (1.0f + erff(v * 0.70710678118654752f));
}

// ---------------------------------------------------------------------------
// small kernels
// ---------------------------------------------------------------------------
__global__ void init_kernel() {
    if (threadIdx.x < NEXP) g_count[threadIdx.x] = 0;
}

__global__ void zero_out_kernel(float* out, size_t n) {
    size_t i = ((size_t)blockIdx.x * blockDim.x + threadIdx.x) * 4;
    if (i < n) *(float4*)&out[i] = make_float4(0.f, 0.f, 0.f, 0.f);
}

// router: 8 warps = 8 tokens/block; rw staged transposed in smem; fused fp16.
__global__ __launch_bounds__(256)
void router_kernel(const float* __restrict__ x,
                   const float* __restrict__ rw,
                   const float* __restrict__ rb,
                   const float* __restrict__ eb,
                   __half* __restrict__ xh) {
    __shared__ float rws[NEXP][DIM];   // 32 KB

    const int tid = threadIdx.x;
    for (int d = tid; d < DIM; d += 256) {
        float4 a = *(const float4*)&rw[(size_t)d * NEXP];
        float4 b = *(const float4*)&rw[(size_t)d * NEXP + 4];
        rws[0][d] = a.x; rws[1][d] = a.y; rws[2][d] = a.z; rws[3][d] = a.w;
        rws[4][d] = b.x; rws[5][d] = b.y; rws[6][d] = b.z; rws[7][d] = b.w;
    }
    __syncthreads();

    const int lane = tid & 31;
    const int t = blockIdx.x * 8 + (tid >> 5);
    const float* xr = x + (size_t)t * DIM;

    float acc[NEXP];
#pragma unroll
    for (int e = 0; e < NEXP; e++) acc[e] = 0.0f;

#pragma unroll
    for (int it = 0; it < 8; it++) {
        const int d = (it * 32 + lane) * 4;
        float4 v = *(const float4*)&xr[d];
        __half h[4];
        h[0] = __float2half_rn(v.x); h[1] = __float2half_rn(v.y);
        h[2] = __float2half_rn(v.z); h[3] = __float2half_rn(v.w);
        *(uint2*)&xh[(size_t)t * DIM + d] = *(uint2*)h;
#pragma unroll
        for (int e = 0; e < NEXP; e++) {
            float4 w = *(const float4*)&rws[e][d];
            acc[e] = fmaf(v.x, w.x, fmaf(v.y, w.y, fmaf(v.z, w.z, fmaf(v.w, w.w, acc[e]))));
        }
    }
#pragma unroll
    for (int off = 16; off > 0; off >>= 1)
#pragma unroll
        for (int e = 0; e < NEXP; e++)
            acc[e] += __shfl_xor_sync(0xFFFFFFFFu, acc[e], off);

    if (lane == 0) {
        float p[NEXP];
        float mx = -1e30f;
#pragma unroll
        for (int e = 0; e < NEXP; e++) { p[e] = acc[e] + rb[e] + eb[e]; mx = fmaxf(mx, p[e]); }
        float z = 0.0f;
#pragma unroll
        for (int e = 0; e < NEXP; e++) { p[e] = expf(p[e] - mx); z += p[e]; }
        float inv = 1.0f / z;
#pragma unroll
        for (int e = 0; e < NEXP; e++) p[e] *= inv;
        int i1 = 0;
#pragma unroll
        for (int e = 1; e < NEXP; e++) if (p[e] > p[i1]) i1 = e;
        int i2 = (i1 == 0) ? 1 : 0;
#pragma unroll
        for (int e = 0; e < NEXP; e++) if (e != i1 && p[e] > p[i2]) i2 = e;
        float s = 1.0f / (p[i1] + p[i2] + 1e-9f);
        g_topki[t * 2 + 0] = i1;  g_topkg[t * 2 + 0] = p[i1] * s;
        g_topki[t * 2 + 1] = i2;  g_topkg[t * 2 + 1] = p[i2] * s;
        atomicAdd(&g_count[i1], 1);
        atomicAdd(&g_count[i2], 1);
    }
}

__global__ void scan_kernel() {
    int o = 0;
    g_offset[0] = 0;
    for (int e = 0; e < NEXP; e++) {
        g_fill[e] = o;
        o += g_count[e];
        g_offset[e + 1] = o;
    }
}

__global__ void scatter_kernel() {
    int idx = blockIdx.x * blockDim.x + threadIdx.x;
    if (idx >= TK_TOT) return;
    int e = g_topki[idx];
    int pos = atomicAdd(&g_fill[e], 1);
    g_tok[pos]  = idx >> 1;
    g_gate[pos] = g_topkg[idx];
}

// src: [E][K][N] fp32 -> dst: [E][N][K] fp16; 64k x 32n per block, 128B writes
__global__ void transpose_w_kernel(const float* __restrict__ src, __half* __restrict__ dst,
                                   int K, int N) {
    __shared__ float tile[64][33];
    size_t base = (size_t)blockIdx.z * K * N;
    int n0 = blockIdx.x * 32, k0 = blockIdx.y * 64;
    int tx = threadIdx.x, ty = threadIdx.y;   // (32, 8)
#pragma unroll
    for (int i = 0; i < 64; i += 8)
        tile[ty + i][tx] = src[base + (size_t)(k0 + ty + i) * N + n0 + tx];
    __syncthreads();
#pragma unroll
    for (int j = 0; j < 4; j++) {
        int r = ty * 4 + j;
        __half2 h = __floats2half2_rn(tile[2 * tx][r], tile[2 * tx + 1][r]);
        *(__half2*)&dst[base + (size_t)(n0 + r) * K + k0 + 2 * tx] = h;
    }
}

// ---------------------------------------------------------------------------
// HMMA GEMM: BM=128 x BN=128, BK=32, 128 threads (4 warps 2x2, 64x64 tiles),
// 4-stage cp.async, padded smem (80B rows), 1 barrier/iter, 2 CTAs/SM.
// KLEN: K covered per CTA; KSTRIDE: row stride of A/B; SPLITS: K-splits
// (blockIdx.z = e*SPLITS + ks; split ks covers k in [ks*KLEN, (ks+1)*KLEN)).
// GEMM1 epilogue: bias + GELU -> fp16 Hh.
// GEMM2 epilogue: gated atomicAdd into fp32 out; bias only from split 0.
// ---------------------------------------------------------------------------
#define BM 128
#define BN 128
#define BK 32
#define STAGES 4
#define STAGE_BYTES (BM * 80)
#define SMEM_TOTAL (2 * STAGES * STAGE_BYTES + BM * 4 + BM * 8 + BN * 4)

template<int KLEN, int KSTRIDE, int SPLITS, bool IS_G1>
__global__ __launch_bounds__(128, 2)
void gemm_kernel(const __half* __restrict__ Asrc,
                 const __half* __restrict__ Bsrc,
                 const float* __restrict__ bias,
                 __half* __restrict__ Hout,
                 float* __restrict__ Yout) {
    constexpr int NB = IS_G1 ? MLP : DIM;
    constexpr int TT = KLEN / BK;

    const int e   = blockIdx.z / SPLITS;
    const int ks  = blockIdx.z % SPLITS;
    const int cnt = g_count[e];
    const int m0  = blockIdx.x * BM;
    if (m0 >= cnt) return;
    const int off = g_offset[e];
    const int n0  = blockIdx.y * BN;
    const int kbase = ks * KLEN;

    extern __shared__ char smem[];
    const uint32_t sb   = smem_u32(smem);
    const uint32_t a_sm = sb;
    const uint32_t b_sm = sb + STAGES * STAGE_BYTES;
    int*   rows_s = (int*)(smem + 2 * STAGES * STAGE_BYTES);   // A-row source
    int*   tok_s  = (int*)(rows_s + BM);                       // output token (G2)
    float* gate_s = (float*)(tok_s + BM);                      // gate (G2)
    float* bias_s = (float*)(gate_s + BM);

    const int tid  = threadIdx.x;
    const int lane = tid & 31;
    const int wid  = tid >> 5;
    const int wm   = (wid & 1) * 64;
    const int wn   = (wid >> 1) * 64;

    {
        int mg = m0 + tid;
        int r  = (mg < cnt) ? mg : (cnt - 1);
        if (IS_G1) {
            rows_s[tid] = g_tok[off + r];
        } else {
            rows_s[tid] = off + r;
            tok_s[tid]  = g_tok[off + r];
            gate_s[tid] = g_gate[off + r];
        }
        bias_s[tid] = bias[(size_t)e * NB + n0 + tid];
    }
    __syncthreads();

    const __half* aG[4]; uint32_t aS[4];
    const __half* bG[4]; uint32_t bS[4];
#pragma unroll
    for (int i = 0; i < 4; i++) {
        int id = tid + i * 128;
        int r = id >> 2, c = id & 3;
        aG[i] = Asrc + (size_t)rows_s[r] * KSTRIDE + kbase + c * 8;
        bG[i] = Bsrc + ((size_t)e * NB + n0 + r) * KSTRIDE + kbase + c * 8;
        aS[i] = a_sm + r * 80 + c * 16;
        bS[i] = b_sm + r * 80 + c * 16;
    }

    auto load_stage = [&](int t, int buf) {
        const int k0 = t * BK;
        const uint32_t so = buf * STAGE_BYTES;
#pragma unroll
        for (int i = 0; i < 4; i++) cp16(aS[i] + so, aG[i] + k0);
#pragma unroll
        for (int i = 0; i < 4; i++) cp16(bS[i] + so, bG[i] + k0);
        cp_commit();
    };

    float acc[4][8][4];
#pragma unroll
    for (int i = 0; i < 4; i++)
#pragma unroll
        for (int j = 0; j < 8; j++)
#pragma unroll
            for (int q = 0; q < 4; q++) acc[i][j][q] = 0.0f;

    load_stage(0, 0);
    load_stage(1, 1);
    load_stage(2, 2);

    const uint32_t a_ld = a_sm + (wm + (lane & 15)) * 80 + (lane >> 4) * 16;
    const uint32_t b_ld = b_sm + (wn + ((lane >> 4) << 3) + (lane & 7)) * 80
                               + (((lane >> 3) & 1) * 16);

    for (int t = 0; t < TT; t++) {
        const int buf = t % STAGES;
        if (t < TT - 2)      asm volatile("cp.async.wait_group 2;" ::: "memory");
        else if (t < TT - 1) asm volatile("cp.async.wait_group 1;" ::: "memory");
        else                 asm volatile("cp.async.wait_group 0;" ::: "memory");
        __syncthreads();

        const uint32_t ao = buf * STAGE_BYTES;
        const uint32_t bo = buf * STAGE_BYTES;

        uint32_t a[2][4][4], b[2][4][4];
#pragma unroll
        for (int kk = 0; kk < 2; kk++) {
#pragma unroll
            for (int i = 0; i < 4; i++)
                ldsm_x4(a[kk][i], a_ld + ao + i * 16 * 80 + kk * 32);
#pragma unroll
            for (int p = 0; p < 4; p++)
                ldsm_x4(b[kk][p], b_ld + bo + p * 16 * 80 + kk * 32);
        }
        // cp.async for t+3 in the ldsm->mma latency shadow
        if (t + 3 < TT) load_stage(t + 3, (t + 3) % STAGES);

#pragma unroll
        for (int kk = 0; kk < 2; kk++)
#pragma unroll
            for (int i = 0; i < 4; i++)
#pragma unroll
                for (int p = 0; p < 4; p++) {
                    mma16816(acc[i][2 * p + 0], a[kk][i], &b[kk][p][0]);
                    mma16816(acc[i][2 * p + 1], a[kk][i], &b[kk][p][2]);
                }
    }

    // ---- epilogue ----
    const int grow = lane >> 2;
    const int gcol = (lane & 3) * 2;
    const float bscale = (ks == 0) ? 1.0f : 0.0f;   // bias only from split 0
#pragma unroll
    for (int i = 0; i < 4; i++) {
        const int rlo = wm + i * 16 + grow;
        const int rhi = rlo + 8;
#pragma unroll
        for (int j = 0; j < 8; j++) {
            const int cb  = wn + j * 8 + gcol;
            const int col = n0 + cb;
            const float b0 = bias_s[cb] * bscale, b1 = bias_s[cb + 1] * bscale;
            if (IS_G1) {
                if (m0 + rlo < cnt) {
                    float v0 = gelu_exact(acc[i][j][0] + b0);
                    float v1 = gelu_exact(acc[i][j][1] + b1);
                    *(__half2*)&Hout[(size_t)(off + m0 + rlo) * MLP + col] =
                        __floats2half2_rn(v0, v1);
                }
                if (m0 + rhi < cnt) {
                    float v0 = gelu_exact(acc[i][j][2] + b0);
                    float v1 = gelu_exact(acc[i][j][3] + b1);
                    *(__half2*)&Hout[(size_t)(off + m0 + rhi) * MLP + col] =
                        __floats2half2_rn(v0, v1);
                }
            } else {
                if (m0 + rlo < cnt) {
                    float g = gate_s[rlo];
                    float* orow = Yout + (size_t)tok_s[rlo] * DIM + col;
                    atomicAdd(&orow[0], g * (acc[i][j][0] + b0));
                    atomicAdd(&orow[1], g * (acc[i][j][1] + b1));
                }
                if (m0 + rhi < cnt) {
                    float g = gate_s[rhi];
                    float* orow = Yout + (size_t)tok_s[rhi] * DIM + col;
                    atomicAdd(&orow[0], g * (acc[i][j][2] + b0));
                    atomicAdd(&orow[1], g * (acc[i][j][3] + b1));
                }
            }
        }
    }
}

// ---------------------------------------------------------------------------
// launch: w1-transpose first on side stream; zero_out last (GEMM2-only dep).
// ---------------------------------------------------------------------------
extern "C" void kernel_launch(void* const* d_in, const int* in_sizes, int n_in,
                              void* d_out, int out_size) {
    const float* hidden = (const float*)d_in[0];
    const float* rw     = (const float*)d_in[1];
    const float* rb     = (const float*)d_in[2];
    const float* eb     = (const float*)d_in[3];
    const float* w1     = (const float*)d_in[4];
    const float* b1     = (const float*)d_in[5];
    const float* w2     = (const float*)d_in[6];
    const float* b2     = (const float*)d_in[7];
    float* out = (float*)d_out;

    // Resolve REAL device addresses of scratch globals (ATS host-shadow trap).
    void *p_xh, *p_w1t, *p_w2t, *p_Hh;
    cudaGetSymbolAddress(&p_xh,  g_xh);
    cudaGetSymbolAddress(&p_w1t, g_w1t);
    cudaGetSymbolAddress(&p_w2t, g_w2t);
    cudaGetSymbolAddress(&p_Hh,  g_Hh);
    __half* xh  = (__half*)p_xh;
    __half* w1t = (__half*)p_w1t;
    __half* w2t = (__half*)p_w2t;
    __half* Hh  = (__half*)p_Hh;

    cudaFuncSetAttribute((const void*)gemm_kernel<DIM, DIM, 1, true>,
                         cudaFuncAttributeMaxDynamicSharedMemorySize, SMEM_TOTAL);
    cudaFuncSetAttribute((const void*)gemm_kernel<DIM, MLP, 4, false>,
                         cudaFuncAttributeMaxDynamicSharedMemorySize, SMEM_TOTAL);

    cudaStream_t s2;
    cudaStreamCreateWithFlags(&s2, cudaStreamNonBlocking);
    cudaEvent_t evF, evW1, evZW2;
    cudaEventCreateWithFlags(&evF,   cudaEventDisableTiming);
    cudaEventCreateWithFlags(&evW1,  cudaEventDisableTiming);
    cudaEventCreateWithFlags(&evZW2, cudaEventDisableTiming);

    init_kernel<<<1, 32>>>();
    cudaEventRecord(evF, 0);
    cudaStreamWaitEvent(s2, evF, 0);

    // side stream: w1 transpose (GEMM1 dep) first, then w2, then zero_out
    {
        dim3 blk(32, 8);
        dim3 t1(MLP / 32, DIM / 64, NEXP);
        transpose_w_kernel<<<t1, blk, 0, s2>>>(w1, w1t, DIM, MLP);
        cudaEventRecord(evW1, s2);
        dim3 t2(DIM / 32, MLP / 64, NEXP);
        transpose_w_kernel<<<t2, blk, 0, s2>>>(w2, w2t, MLP, DIM);
        size_t n = (size_t)out_size;
        zero_out_kernel<<<(unsigned)((n / 4 + 255) / 256), 256, 0, s2>>>(out, n);
        cudaEventRecord(evZW2, s2);
    }

    // main stream: router chain
    router_kernel<<<T_TOKENS / 8, 256>>>(hidden, rw, rb, eb, xh);
    scan_kernel<<<1, 1>>>();
    scatter_kernel<<<TK_TOT / 256, 256>>>();

    cudaStreamWaitEvent(0, evW1, 0);
    {
        dim3 grid(T_TOKENS / BM, MLP / BN, NEXP);
        gemm_kernel<DIM, DIM, 1, true><<<grid, 128, SMEM_TOTAL>>>(xh, w1t, b1, Hh, nullptr);
    }
    cudaStreamWaitEvent(0, evZW2, 0);
    {
        dim3 grid(T_TOKENS / BM, DIM / BN, NEXP * 4);   // (64, 8, 32): K-split x4
        gemm_kernel<DIM, MLP, 4, false><<<grid, 128, SMEM_TOTAL>>>(Hh, w2t, b2, nullptr, out);
    }
}

// round 17
// speedup vs baseline: 1.0353x; 1.0353x over previous
#include <cuda_runtime.h>
#include <cuda_fp16.h>
#include <math.h>
#include <stdint.h>

// ---------------------------------------------------------------------------
// MoE: T=8192 tokens, D=1024, MLP=4096, E=8, top-2.
// fp16 HMMA path. R17: exact R15 config (927.8us) with GEMM2's gated-add
// epilogue vectorized via red.global.add.v2.f32 (halves RED issue count).
// ---------------------------------------------------------------------------

#define T_TOKENS 8192
#define DIM      1024
#define MLP      4096
#define NEXP     8
#define TK_TOT   (T_TOKENS * 2)

// ---- scratch (device globals; no cudaMalloc allowed) ----
__device__ int   g_count[NEXP];
__device__ int   g_offset[NEXP + 1];
__device__ int   g_fill[NEXP];
__device__ int   g_topki[TK_TOT];
__device__ float g_topkg[TK_TOT];
__device__ int   g_tok[TK_TOT];
__device__ float g_gate[TK_TOT];
__device__ __align__(16) __half g_xh [(size_t)T_TOKENS * DIM];
__device__ __align__(16) __half g_w1t[(size_t)NEXP * MLP * DIM];  // [e][n][k]
__device__ __align__(16) __half g_w2t[(size_t)NEXP * DIM * MLP];  // [e][n][k]
__device__ __align__(16) __half g_Hh [(size_t)TK_TOT * MLP];

// ---------------------------------------------------------------------------
// PTX helpers (plain-target features only; no 'a'-suffix instructions)
// ---------------------------------------------------------------------------
__device__ __forceinline__ uint32_t smem_u32(const void* p) {
    uint32_t a;
    asm("{ .reg .u64 t; cvta.to.shared.u64 t, %1; cvt.u32.u64 %0, t; }" : "=r"(a) : "l"(p));
    return a;
}
__device__ __forceinline__ void cp16(uint32_t dst, const void* src) {
    asm volatile("cp.async.cg.shared.global [%0], [%1], 16;" :: "r"(dst), "l"(src) : "memory");
}
__device__ __forceinline__ void cp_commit() { asm volatile("cp.async.commit_group;" ::: "memory"); }

__device__ __forceinline__ void ldsm_x4(uint32_t* r, uint32_t addr) {
    asm volatile("ldmatrix.sync.aligned.m8n8.x4.shared.b16 {%0,%1,%2,%3}, [%4];"
                 : "=r"(r[0]), "=r"(r[1]), "=r"(r[2]), "=r"(r[3]) : "r"(addr));
}
__device__ __forceinline__ void mma16816(float* c, const uint32_t* a, const uint32_t* b) {
    asm volatile("mma.sync.aligned.m16n8k16.row.col.f32.f16.f16.f32 "
                 "{%0,%1,%2,%3}, {%4,%5,%6,%7}, {%8,%9}, {%0,%1,%2,%3};"
                 : "+f"(c[0]), "+f"(c[1]), "+f"(c[2]), "+f"(c[3])
                 : "r"(a[0]), "r"(a[1]), "r"(a[2]), "r"(a[3]), "r"(b[0]), "r"(b[1]));
}
// vectorized global fp32 reduction (sm_90+ plain feature)
__device__ __forceinline__ void red_add_v2(float* ptr, float v0, float v1) {
    asm volatile("red.global.add.v2.f32 [%0], {%1, %2};"
                 :: "l"(ptr), "f"(v0), "f"(v1) : "memory");
}

__device__ __forceinline__ float gelu_exact(float v) {
    return 0.5f * v * (1.0f + erff(v * 0.70710678118654752f));
}

// ---------------------------------------------------------------------------
// small kernels
// ---------------------------------------------------------------------------
__global__ void init_kernel() {
    if (threadIdx.x < NEXP) g_count[threadIdx.x] = 0;
}

__global__ void zero_out_kernel(float* out, size_t n) {
    size_t i = ((size_t)blockIdx.x * blockDim.x + threadIdx.x) * 4;
    if (i < n) *(float4*)&out[i] = make_float4(0.f, 0.f, 0.f, 0.f);
}

// router: 8 warps = 8 tokens/block; rw staged transposed in smem; fused fp16.
__global__ __launch_bounds__(256)
void router_kernel(const float* __restrict__ x,
                   const float* __restrict__ rw,
                   const float* __restrict__ rb,
                   const float* __restrict__ eb,
                   __half* __restrict__ xh) {
    __shared__ float rws[NEXP][DIM];   // 32 KB

    const int tid = threadIdx.x;
    for (int d = tid; d < DIM; d += 256) {
        float4 a = *(const float4*)&rw[(size_t)d * NEXP];
        float4 b = *(const float4*)&rw[(size_t)d * NEXP + 4];
        rws[0][d] = a.x; rws[1][d] = a.y; rws[2][d] = a.z; rws[3][d] = a.w;
        rws[4][d] = b.x; rws[5][d] = b.y; rws[6][d] = b.z; rws[7][d] = b.w;
    }
    __syncthreads();

    const int lane = tid & 31;
    const int t = blockIdx.x * 8 + (tid >> 5);
    const float* xr = x + (size_t)t * DIM;

    float acc[NEXP];
#pragma unroll
    for (int e = 0; e < NEXP; e++) acc[e] = 0.0f;

#pragma unroll
    for (int it = 0; it < 8; it++) {
        const int d = (it * 32 + lane) * 4;
        float4 v = *(const float4*)&xr[d];
        __half h[4];
        h[0] = __float2half_rn(v.x); h[1] = __float2half_rn(v.y);
        h[2] = __float2half_rn(v.z); h[3] = __float2half_rn(v.w);
        *(uint2*)&xh[(size_t)t * DIM + d] = *(uint2*)h;
#pragma unroll
        for (int e = 0; e < NEXP; e++) {
            float4 w = *(const float4*)&rws[e][d];
            acc[e] = fmaf(v.x, w.x, fmaf(v.y, w.y, fmaf(v.z, w.z, fmaf(v.w, w.w, acc[e]))));
        }
    }
#pragma unroll
    for (int off = 16; off > 0; off >>= 1)
#pragma unroll
        for (int e = 0; e < NEXP; e++)
            acc[e] += __shfl_xor_sync(0xFFFFFFFFu, acc[e], off);

    if (lane == 0) {
        float p[NEXP];
        float mx = -1e30f;
#pragma unroll
        for (int e = 0; e < NEXP; e++) { p[e] = acc[e] + rb[e] + eb[e]; mx = fmaxf(mx, p[e]); }
        float z = 0.0f;
#pragma unroll
        for (int e = 0; e < NEXP; e++) { p[e] = expf(p[e] - mx); z += p[e]; }
        float inv = 1.0f / z;
#pragma unroll
        for (int e = 0; e < NEXP; e++) p[e] *= inv;
        int i1 = 0;
#pragma unroll
        for (int e = 1; e < NEXP; e++) if (p[e] > p[i1]) i1 = e;
        int i2 = (i1 == 0) ? 1 : 0;
#pragma unroll
        for (int e = 0; e < NEXP; e++) if (e != i1 && p[e] > p[i2]) i2 = e;
        float s = 1.0f / (p[i1] + p[i2] + 1e-9f);
        g_topki[t * 2 + 0] = i1;  g_topkg[t * 2 + 0] = p[i1] * s;
        g_topki[t * 2 + 1] = i2;  g_topkg[t * 2 + 1] = p[i2] * s;
        atomicAdd(&g_count[i1], 1);
        atomicAdd(&g_count[i2], 1);
    }
}

__global__ void scan_kernel() {
    int o = 0;
    g_offset[0] = 0;
    for (int e = 0; e < NEXP; e++) {
        g_fill[e] = o;
        o += g_count[e];
        g_offset[e + 1] = o;
    }
}

__global__ void scatter_kernel() {
    int idx = blockIdx.x * blockDim.x + threadIdx.x;
    if (idx >= TK_TOT) return;
    int e = g_topki[idx];
    int pos = atomicAdd(&g_fill[e], 1);
    g_tok[pos]  = idx >> 1;
    g_gate[pos] = g_topkg[idx];
}

// src: [E][K][N] fp32 -> dst: [E][N][K] fp16; 64k x 32n per block, 128B writes
__global__ void transpose_w_kernel(const float* __restrict__ src, __half* __restrict__ dst,
                                   int K, int N) {
    __shared__ float tile[64][33];
    size_t base = (size_t)blockIdx.z * K * N;
    int n0 = blockIdx.x * 32, k0 = blockIdx.y * 64;
    int tx = threadIdx.x, ty = threadIdx.y;   // (32, 8)
#pragma unroll
    for (int i = 0; i < 64; i += 8)
        tile[ty + i][tx] = src[base + (size_t)(k0 + ty + i) * N + n0 + tx];
    __syncthreads();
#pragma unroll
    for (int j = 0; j < 4; j++) {
        int r = ty * 4 + j;
        __half2 h = __floats2half2_rn(tile[2 * tx][r], tile[2 * tx + 1][r]);
        *(__half2*)&dst[base + (size_t)(n0 + r) * K + k0 + 2 * tx] = h;
    }
}

// ---------------------------------------------------------------------------
// HMMA GEMM: BM=128 x BN=128, BK=32, 128 threads (4 warps 2x2, 64x64 tiles),
// 4-stage cp.async, padded smem (80B rows), 1 barrier/iter, 2 CTAs/SM.
// GEMM1 epilogue: bias + GELU -> fp16 Hh.
// GEMM2 epilogue: gated red.global.add.v2.f32 into fp32 out (fused combine).
// ---------------------------------------------------------------------------
#define BM 128
#define BN 128
#define BK 32
#define STAGES 4
#define STAGE_BYTES (BM * 80)
#define SMEM_TOTAL (2 * STAGES * STAGE_BYTES + BM * 4 + BM * 8 + BN * 4)

template<int KTOT, bool IS_G1>
__global__ __launch_bounds__(128, 2)
void gemm_kernel(const __half* __restrict__ Asrc,
                 const __half* __restrict__ Bsrc,
                 const float* __restrict__ bias,
                 __half* __restrict__ Hout,
                 float* __restrict__ Yout) {
    constexpr int NB = IS_G1 ? MLP : DIM;
    constexpr int TT = KTOT / BK;

    const int e   = blockIdx.z;
    const int cnt = g_count[e];
    const int m0  = blockIdx.x * BM;
    if (m0 >= cnt) return;
    const int off = g_offset[e];
    const int n0  = blockIdx.y * BN;

    extern __shared__ char smem[];
    const uint32_t sb   = smem_u32(smem);
    const uint32_t a_sm = sb;
    const uint32_t b_sm = sb + STAGES * STAGE_BYTES;
    int*   rows_s = (int*)(smem + 2 * STAGES * STAGE_BYTES);   // A-row source
    int*   tok_s  = (int*)(rows_s + BM);                       // output token (G2)
    float* gate_s = (float*)(tok_s + BM);                      // gate (G2)
    float* bias_s = (float*)(gate_s + BM);

    const int tid  = threadIdx.x;
    const int lane = tid & 31;
    const int wid  = tid >> 5;
    const int wm   = (wid & 1) * 64;
    const int wn   = (wid >> 1) * 64;

    {
        int mg = m0 + tid;
        int r  = (mg < cnt) ? mg : (cnt - 1);
        if (IS_G1) {
            rows_s[tid] = g_tok[off + r];
        } else {
            rows_s[tid] = off + r;
            tok_s[tid]  = g_tok[off + r];
            gate_s[tid] = g_gate[off + r];
        }
        bias_s[tid] = bias[(size_t)e * NB + n0 + tid];
    }
    __syncthreads();

    const __half* aG[4]; uint32_t aS[4];
    const __half* bG[4]; uint32_t bS[4];
#pragma unroll
    for (int i = 0; i < 4; i++) {
        int id = tid + i * 128;
        int r = id >> 2, c = id & 3;
        aG[i] = Asrc + (size_t)rows_s[r] * KTOT + c * 8;
        bG[i] = Bsrc + ((size_t)e * NB + n0 + r) * KTOT + c * 8;
        aS[i] = a_sm + r * 80 + c * 16;
        bS[i] = b_sm + r * 80 + c * 16;
    }

    auto load_stage = [&](int t, int buf) {
        const int k0 = t * BK;
        const uint32_t so = buf * STAGE_BYTES;
#pragma unroll
        for (int i = 0; i < 4; i++) cp16(aS[i] + so, aG[i] + k0);
#pragma unroll
        for (int i = 0; i < 4; i++) cp16(bS[i] + so, bG[i] + k0);
        cp_commit();
    };

    float acc[4][8][4];
#pragma unroll
    for (int i = 0; i < 4; i++)
#pragma unroll
        for (int j = 0; j < 8; j++)
#pragma unroll
            for (int q = 0; q < 4; q++) acc[i][j][q] = 0.0f;

    load_stage(0, 0);
    load_stage(1, 1);
    load_stage(2, 2);

    const uint32_t a_ld = a_sm + (wm + (lane & 15)) * 80 + (lane >> 4) * 16;
    const uint32_t b_ld = b_sm + (wn + ((lane >> 4) << 3) + (lane & 7)) * 80
                               + (((lane >> 3) & 1) * 16);

    for (int t = 0; t < TT; t++) {
        const int buf = t % STAGES;
        if (t < TT - 2)      asm volatile("cp.async.wait_group 2;" ::: "memory");
        else if (t < TT - 1) asm volatile("cp.async.wait_group 1;" ::: "memory");
        else                 asm volatile("cp.async.wait_group 0;" ::: "memory");
        __syncthreads();

        const uint32_t ao = buf * STAGE_BYTES;
        const uint32_t bo = buf * STAGE_BYTES;

        uint32_t a[2][4][4], b[2][4][4];
#pragma unroll
        for (int kk = 0; kk < 2; kk++) {
#pragma unroll
            for (int i = 0; i < 4; i++)
                ldsm_x4(a[kk][i], a_ld + ao + i * 16 * 80 + kk * 32);
#pragma unroll
            for (int p = 0; p < 4; p++)
                ldsm_x4(b[kk][p], b_ld + bo + p * 16 * 80 + kk * 32);
        }
        // cp.async for t+3 in the ldsm->mma latency shadow
        if (t + 3 < TT) load_stage(t + 3, (t + 3) % STAGES);

#pragma unroll
        for (int kk = 0; kk < 2; kk++)
#pragma unroll
            for (int i = 0; i < 4; i++)
#pragma unroll
                for (int p = 0; p < 4; p++) {
                    mma16816(acc[i][2 * p + 0], a[kk][i], &b[kk][p][0]);
                    mma16816(acc[i][2 * p + 1], a[kk][i], &b[kk][p][2]);
                }
    }

    // ---- epilogue ----
    const int grow = lane >> 2;
    const int gcol = (lane & 3) * 2;
#pragma unroll
    for (int i = 0; i < 4; i++) {
        const int rlo = wm + i * 16 + grow;
        const int rhi = rlo + 8;
#pragma unroll
        for (int j = 0; j < 8; j++) {
            const int cb  = wn + j * 8 + gcol;
            const int col = n0 + cb;
            const float b0 = bias_s[cb], b1 = bias_s[cb + 1];
            if (IS_G1) {
                if (m0 + rlo < cnt) {
                    float v0 = gelu_exact(acc[i][j][0] + b0);
                    float v1 = gelu_exact(acc[i][j][1] + b1);
                    *(__half2*)&Hout[(size_t)(off + m0 + rlo) * MLP + col] =
                        __floats2half2_rn(v0, v1);
                }
                if (m0 + rhi < cnt) {
                    float v0 = gelu_exact(acc[i][j][2] + b0);
                    float v1 = gelu_exact(acc[i][j][3] + b1);
                    *(__half2*)&Hout[(size_t)(off + m0 + rhi) * MLP + col] =
                        __floats2half2_rn(v0, v1);
                }
            } else {
                if (m0 + rlo < cnt) {
                    float g = gate_s[rlo];
                    float* orow = Yout + (size_t)tok_s[rlo] * DIM + col;
                    red_add_v2(orow, g * (acc[i][j][0] + b0), g * (acc[i][j][1] + b1));
                }
                if (m0 + rhi < cnt) {
                    float g = gate_s[rhi];
                    float* orow = Yout + (size_t)tok_s[rhi] * DIM + col;
                    red_add_v2(orow, g * (acc[i][j][2] + b0), g * (acc[i][j][3] + b1));
                }
            }
        }
    }
}

// ---------------------------------------------------------------------------
// launch: w1-transpose first on side stream; zero_out last (GEMM2-only dep).
// ---------------------------------------------------------------------------
extern "C" void kernel_launch(void* const* d_in, const int* in_sizes, int n_in,
                              void* d_out, int out_size) {
    const float* hidden = (const float*)d_in[0];
    const float* rw     = (const float*)d_in[1];
    const float* rb     = (const float*)d_in[2];
    const float* eb     = (const float*)d_in[3];
    const float* w1     = (const float*)d_in[4];
    const float* b1     = (const float*)d_in[5];
    const float* w2     = (const float*)d_in[6];
    const float* b2     = (const float*)d_in[7];
    float* out = (float*)d_out;

    // Resolve REAL device addresses of scratch globals (ATS host-shadow trap).
    void *p_xh, *p_w1t, *p_w2t, *p_Hh;
    cudaGetSymbolAddress(&p_xh,  g_xh);
    cudaGetSymbolAddress(&p_w1t, g_w1t);
    cudaGetSymbolAddress(&p_w2t, g_w2t);
    cudaGetSymbolAddress(&p_Hh,  g_Hh);
    __half* xh  = (__half*)p_xh;
    __half* w1t = (__half*)p_w1t;
    __half* w2t = (__half*)p_w2t;
    __half* Hh  = (__half*)p_Hh;

    cudaFuncSetAttribute(gemm_kernel<DIM, true>,
                         cudaFuncAttributeMaxDynamicSharedMemorySize, SMEM_TOTAL);
    cudaFuncSetAttribute(gemm_kernel<MLP, false>,
                         cudaFuncAttributeMaxDynamicSharedMemorySize, SMEM_TOTAL);

    cudaStream_t s2;
    cudaStreamCreateWithFlags(&s2, cudaStreamNonBlocking);
    cudaEvent_t evF, evW1, evZW2;
    cudaEventCreateWithFlags(&evF,   cudaEventDisableTiming);
    cudaEventCreateWithFlags(&evW1,  cudaEventDisableTiming);
    cudaEventCreateWithFlags(&evZW2, cudaEventDisableTiming);

    init_kernel<<<1, 32>>>();
    cudaEventRecord(evF, 0);
    cudaStreamWaitEvent(s2, evF, 0);

    // side stream: w1 transpose (GEMM1 dep) first, then w2, then zero_out
    {
        dim3 blk(32, 8);
        dim3 t1(MLP / 32, DIM / 64, NEXP);
        transpose_w_kernel<<<t1, blk, 0, s2>>>(w1, w1t, DIM, MLP);
        cudaEventRecord(evW1, s2);
        dim3 t2(DIM / 32, MLP / 64, NEXP);
        transpose_w_kernel<<<t2, blk, 0, s2>>>(w2, w2t, MLP, DIM);
        size_t n = (size_t)out_size;
        zero_out_kernel<<<(unsigned)((n / 4 + 255) / 256), 256, 0, s2>>>(out, n);
        cudaEventRecord(evZW2, s2);
    }

    // main stream: router chain
    router_kernel<<<T_TOKENS / 8, 256>>>(hidden, rw, rb, eb, xh);
    scan_kernel<<<1, 1>>>();
    scatter_kernel<<<TK_TOT / 256, 256>>>();

    cudaStreamWaitEvent(0, evW1, 0);
    {
        dim3 grid(T_TOKENS / BM, MLP / BN, NEXP);
        gemm_kernel<DIM, true><<<grid, 128, SMEM_TOTAL>>>(xh, w1t, b1, Hh, nullptr);
    }
    cudaStreamWaitEvent(0, evZW2, 0);
    {
        dim3 grid(T_TOKENS / BM, DIM / BN, NEXP);
        gemm_kernel<MLP, false><<<grid, 128, SMEM_TOTAL>>>(Hh, w2t, b2, nullptr, out);
    }
}